// round 14
// baseline (speedup 1.0000x reference)
#include <cuda_runtime.h>
#include <cstdint>
#include <cstddef>

#define B_   32
#define C_   256
#define HW_  3136
#define OC_  256
#define PW   58                            // padded width/height
#define PQ   3492                          // 58*58 + 128 tail pad rows

// ---------------- scratch (device globals) ----------------
__device__ float d_mu[B_ * 8];
__device__ float d_rs[B_ * 8];
__device__ float d_scale[OC_];             // alpha_oc * a_c / 255
__device__ unsigned char d_hq[(size_t)B_ * PQ * 256];   // padded NHWC u8
__device__ signed char  d_ws[9 * 256 * 256];            // [tap][oc][ic] in {-1,0,1}

// ======================= PTX helpers =======================
__device__ __forceinline__ uint32_t smem_u32(const void* p) {
    uint32_t a;
    asm("{ .reg .u64 t; cvta.to.shared.u64 t, %1; cvt.u32.u64 %0, t; }" : "=r"(a) : "l"(p));
    return a;
}
#define CP16(dst, src) \
    asm volatile("cp.async.cg.shared.global [%0], [%1], 16;" :: "r"(dst), "l"(src) : "memory")
#define CP_COMMIT() asm volatile("cp.async.commit_group;" ::: "memory")
#define CP_WAIT3()  asm volatile("cp.async.wait_group 3;" ::: "memory")

__device__ __forceinline__ void ldsm4(uint32_t* r, uint32_t addr) {
    asm volatile("ldmatrix.sync.aligned.m8n8.x4.shared.b16 {%0,%1,%2,%3}, [%4];"
                 : "=r"(r[0]), "=r"(r[1]), "=r"(r[2]), "=r"(r[3]) : "r"(addr));
}
__device__ __forceinline__ void ldsm2(uint32_t* r, uint32_t addr) {
    asm volatile("ldmatrix.sync.aligned.m8n8.x2.shared.b16 {%0,%1}, [%2];"
                 : "=r"(r[0]), "=r"(r[1]) : "r"(addr));
}
__device__ __forceinline__ void mma_u8s8(int* c, const uint32_t* a, const uint32_t* b) {
    asm volatile(
        "mma.sync.aligned.m16n8k32.row.col.s32.u8.s8.s32 "
        "{%0,%1,%2,%3}, {%4,%5,%6,%7}, {%8,%9}, {%0,%1,%2,%3};"
        : "+r"(c[0]), "+r"(c[1]), "+r"(c[2]), "+r"(c[3])
        : "r"(a[0]), "r"(a[1]), "r"(a[2]), "r"(a[3]), "r"(b[0]), "r"(b[1]));
}
__device__ __forceinline__ int dp4a_us(unsigned a, unsigned b, int c) {
    int d;
    asm("dp4a.u32.s32 %0, %1, %2, %3;" : "=r"(d) : "r"(a), "r"(b), "r"(c));
    return d;
}

// ---------------- kernel 1: ternarize weights -> s8 [tap][oc][ic] ----------------
__global__ void tern_kernel(const float* __restrict__ w,
                            const float* __restrict__ a_ptr) {
    int oc = blockIdx.x, tid = threadIdx.x;
    const float* wp = w + (size_t)oc * 2304;
    __shared__ float red[256], red2[256];
    __shared__ float t_sh;

    float s = 0.f;
    for (int i = tid; i < 2304; i += 256) s += fabsf(wp[i]);
    red[tid] = s;
    __syncthreads();
    for (int o = 128; o; o >>= 1) {
        if (tid < o) red[tid] += red[tid + o];
        __syncthreads();
    }
    if (tid == 0) t_sh = 0.05f * red[0] / 2304.0f;
    __syncthreads();
    float t = t_sh;

    float sa = 0.f, sm = 0.f;
    for (int i = tid; i < 2304; i += 256) {
        float aw = fabsf(wp[i]);
        if (aw > t) { sa += aw; sm += 1.f; }
    }
    red[tid] = sa; red2[tid] = sm;
    __syncthreads();
    for (int o = 128; o; o >>= 1) {
        if (tid < o) { red[tid] += red[tid + o]; red2[tid] += red2[tid + o]; }
        __syncthreads();
    }
    if (tid == 0) {
        float alpha = red[0] / (red2[0] + 1e-8f);
        float a_c = fmaxf(a_ptr[0], 0.f) + 1e-8f;
        d_scale[oc] = alpha * a_c / 255.0f;
    }
    for (int i = tid; i < 2304; i += 256) {
        float wv = wp[i];
        signed char q = (fabsf(wv) > t) ? (wv > 0.f ? (signed char)1 : (signed char)-1)
                                        : (signed char)0;
        int ic = i / 9, k = i - ic * 9;    // tap = ky*3+kx
        d_ws[((size_t)k * 256 + oc) * 256 + ic] = q;
    }
}

// ---------------- kernel 2: GroupNorm statistics ----------------
__global__ void gn_stats_kernel(const float* __restrict__ x) {
    int bg = blockIdx.x;
    int b = bg >> 3, g = bg & 7;
    const float4* xp = (const float4*)(x + ((size_t)b * C_ + (size_t)g * 32) * HW_);
    const int N4 = 32 * HW_ / 4;
    int tid = threadIdx.x;
    float s = 0.f, s2 = 0.f;
#pragma unroll 4
    for (int i = tid; i < N4; i += 512) {
        float4 v = xp[i];
        s += v.x + v.y + v.z + v.w;
        s2 += v.x * v.x + v.y * v.y + v.z * v.z + v.w * v.w;
    }
    __shared__ float r1[512], r2[512];
    r1[tid] = s; r2[tid] = s2;
    __syncthreads();
    for (int o = 256; o; o >>= 1) {
        if (tid < o) { r1[tid] += r1[tid + o]; r2[tid] += r2[tid + o]; }
        __syncthreads();
    }
    if (tid == 0) {
        const float N = (float)(32 * HW_);
        float mu = r1[0] / N;
        float var = r2[0] / N - mu * mu;
        d_mu[bg] = mu;
        d_rs[bg] = rsqrtf(var + 1e-5f);
    }
}

// ---------------- kernel 3: GN + ReLU^2 + PACT quant + pad-zero (fused) ----------
__global__ void quant_kernel(const float* __restrict__ x,
                             const float* __restrict__ gamma,
                             const float* __restrict__ beta,
                             const float* __restrict__ a_ptr) {
    int b = blockIdx.z;
    int tx = threadIdx.x, ty = threadIdx.y;
    int tid = ty * 32 + tx;

    if (blockIdx.x >= 98) {                // pad-zero blocks
        if (blockIdx.y != 0) return;
        int slot = (blockIdx.x - 98) * 30 + (tid >> 3);
        if (slot >= 356) return;
        int r;
        if (slot < 58)        r = slot;                      // y=0
        else if (slot < 116)  r = 3306 + (slot - 58);        // y=57
        else if (slot < 172)  r = (slot - 115) * PW;         // x=0, y=1..56
        else if (slot < 228)  r = (slot - 171) * PW + 57;    // x=57, y=1..56
        else                  r = 3364 + (slot - 228);       // tail overread rows
        uint4* dst = (uint4*)(d_hq + ((size_t)b * PQ + r) * 256 + (tid & 7) * 32);
        dst[0] = make_uint4(0, 0, 0, 0);
        dst[1] = make_uint4(0, 0, 0, 0);
        return;
    }

    __shared__ unsigned char tile[32][33];
    int c0 = blockIdx.y * 32;
    int p0 = blockIdx.x * 32;

    float a_c = fmaxf(a_ptr[0], 0.f) + 1e-8f;
    float S = 255.f / a_c;
    float mu = d_mu[b * 8 + blockIdx.y];
    float rs = d_rs[b * 8 + blockIdx.y];

#pragma unroll
    for (int i = 0; i < 4; i++) {
        int cl = ty + i * 8;
        int c = c0 + cl;
        float v = x[((size_t)b * C_ + c) * HW_ + p0 + tx];
        float xn = (v - mu) * rs * gamma[c] + beta[c];
        float r = fmaxf(xn, 0.f);
        float h = r * r;
        float yv = fminf(h, a_c);
        tile[cl][tx] = (unsigned char)(int)rintf(yv * S);
    }
    __syncthreads();
#pragma unroll
    for (int i = 0; i < 4; i++) {
        int p = p0 + ty + i * 8;           // valid pixel 0..3135
        int y = p / 56, xx = p - y * 56;
        size_t r = (size_t)(y + 1) * PW + (xx + 1);
        d_hq[((size_t)b * PQ + r) * 256 + c0 + tx] = tile[tx][ty + i * 8];
    }
}

// ---------------- kernel 4: intra-CTA hybrid conv, 128x64 tiles ----------------
// 3200 identical CTAs: b = bid/100, n0 = ((bid%100)/25)*64, q0 = ((bid%100)%25)*128.
// Warps 0-5: IMMA on oc cols 0..47 (warp tile 64x16, warp_m = wid&1, warp_n = wid>>1).
// Warps 6-7: dp4a on oc cols 48..63 (8px x 4oc per thread).
// Every SM carries the same 3:1 tensor:fma mix -> no placement variance.
#define NST 5
#define STAGE_B 15360
#define SMEM_CONV (NST * STAGE_B)

__global__ void __launch_bounds__(256, 3)
conv_mma_kernel(const float* __restrict__ bias, float* __restrict__ out) {
    extern __shared__ char smem[];
    uint32_t sbase = smem_u32(smem);
    int tid = threadIdx.x;
    int wid = tid >> 5, lane = tid & 31;
    int bid = blockIdx.x;
    int b = bid / 100;
    int rem = bid - b * 100;
    int n0 = (rem / 25) * 64;
    int q0 = (rem % 25) * 128;
    bool isIMMA = wid < 6;

    // loaders: tid<128 -> A row tid; tid in [128,192) -> B row tid-128; warps 6,7 none
    bool isA = tid < 128;
    bool isLd = tid < 192;
    int lrow = isA ? tid : tid - 128;
    int lsw = (lrow >> 3) & 3;
    uint32_t sdst0 = sbase + (isA ? 0u : 10240u) + (uint32_t)lrow * 80u;

    const char* gbase;
    if (isA) {
        int q = q0 + lrow;                 // tail tiles read zeroed pad rows
        int y = q / 56, xx = q - y * 56;
        gbase = (const char*)(d_hq + ((size_t)b * PQ + (size_t)(y * PW + xx)) * 256);
    } else {
        gbase = (const char*)(d_ws + (size_t)(n0 + lrow) * 256);
    }

    auto issue = [&](int s) {
        int st = s % NST;
        if (isLd) {
            int tap = s >> 2, cc = s & 3;
            const char* g;
            if (isA) {
                int ky = tap / 3, kx = tap - ky * 3;
                g = gbase + (size_t)(ky * PW + kx) * 256 + cc * 64;
            } else {
                g = gbase + (size_t)tap * 65536 + cc * 64;
            }
            uint32_t d = sdst0 + (uint32_t)st * STAGE_B;
            CP16(d + ((0 ^ lsw) & 3) * 16, g);
            CP16(d + ((1 ^ lsw) & 3) * 16, g + 16);
            CP16(d + ((2 ^ lsw) & 3) * 16, g + 32);
            CP16(d + ((3 ^ lsw) & 3) * 16, g + 48);
        }
        CP_COMMIT();
    };

    // 32 accumulator regs (disjoint role lifetimes)
    int acc[32];
#pragma unroll
    for (int i = 0; i < 32; i++) acc[i] = 0;

    // ---- IMMA geometry (warps 0-5): warp tile 64x16, cols 0..47 ----
    int warp_m = wid & 1, warp_n = wid >> 1;       // warp_n in 0..2 for wid<6
    int grp = lane >> 3, r8 = lane & 7;
    uint32_t a_base[4]; int a_swz[4]; int a_cb = grp >> 1;
#pragma unroll
    for (int t = 0; t < 4; t++) {
        int row = warp_m * 64 + t * 16 + (grp & 1) * 8 + r8;
        a_base[t] = sbase + (uint32_t)row * 80u;
        a_swz[t] = (row >> 3) & 3;
    }
    int bl = lane & 15;
    uint32_t b_base[2]; int b_swz[2]; int b_cb = bl >> 3;
#pragma unroll
    for (int u = 0; u < 2; u++) {
        int row = warp_n * 16 + u * 8 + (bl & 7);  // rows 0..47
        b_base[u] = sbase + 10240u + (uint32_t)row * 80u;
        b_swz[u] = (row >> 3) & 3;
    }

    // ---- dp4a geometry (warps 6,7): 8 px x 4 oc per thread, oc rows 48..63 ----
    int dtid = tid - 192;                  // 0..63 (valid when wid >= 6)
    int pblk = dtid & 15;                  // px block: rows pblk*8 + i
    int og = (dtid >> 4) & 3;              // oc group: rows 48 + og*4 + j
    const char* sA = smem;
    const char* sB = smem + 10240;
    int bkey[4];
#pragma unroll
    for (int j = 0; j < 4; j++)
        bkey[j] = ((48 + og * 4 + j) >> 3) & 3;

    issue(0); issue(1); issue(2); issue(3);

#pragma unroll 1
    for (int s = 0; s < 36; s++) {
        int st = s % NST;
        CP_WAIT3();
        __syncthreads();
        if (s + 4 < 36) issue(s + 4);
        else CP_COMMIT();
        uint32_t so = (uint32_t)st * STAGE_B;

        if (isIMMA) {
#pragma unroll
            for (int ks = 0; ks < 2; ks++) {
                uint32_t afr[4][4], bfr[2][2];
#pragma unroll
                for (int t = 0; t < 4; t++) {
                    uint32_t c = (uint32_t)(((ks * 2 + a_cb) ^ a_swz[t]) & 3) * 16u;
                    ldsm4(afr[t], a_base[t] + so + c);
                }
#pragma unroll
                for (int u = 0; u < 2; u++) {
                    uint32_t c = (uint32_t)(((ks * 2 + b_cb) ^ b_swz[u]) & 3) * 16u;
                    ldsm2(bfr[u], b_base[u] + so + c);
                }
#pragma unroll
                for (int t = 0; t < 4; t++)
#pragma unroll
                    for (int u = 0; u < 2; u++)
                        mma_u8s8(&acc[(t * 2 + u) * 4], afr[t], bfr[u]);
            }
        } else {
            const char* pA = sA + so;
            const char* pB = sB + so;
#pragma unroll 1
            for (int kb = 0; kb < 4; kb++) {
                uint32_t ca = (uint32_t)((kb ^ pblk) & 3) * 16u;  // row>>3 == pblk
                uint4 av[8];
#pragma unroll
                for (int i = 0; i < 8; i++)
                    av[i] = *(const uint4*)(pA + (pblk * 8 + i) * 80 + ca);
#pragma unroll
                for (int j = 0; j < 4; j++) {
                    uint32_t cb = (uint32_t)((kb ^ bkey[j]) & 3) * 16u;
                    uint4 bv = *(const uint4*)(pB + (48 + og * 4 + j) * 80 + cb);
#pragma unroll
                    for (int i = 0; i < 8; i++) {
                        int v = acc[i * 4 + j];
                        v = dp4a_us(av[i].x, bv.x, v);
                        v = dp4a_us(av[i].y, bv.y, v);
                        v = dp4a_us(av[i].z, bv.z, v);
                        v = dp4a_us(av[i].w, bv.w, v);
                        acc[i * 4 + j] = v;
                    }
                }
            }
        }
    }

    // ---------------- epilogue: stage via smem, coalesced NCHW stores --------
    __syncthreads();
    int* sep = (int*)smem;                // [64 oc][pitch 132]
    if (isIMMA) {
#pragma unroll
        for (int t = 0; t < 4; t++) {
            int m = warp_m * 64 + t * 16 + (lane >> 2);
#pragma unroll
            for (int u = 0; u < 2; u++) {
                int n = warp_n * 16 + u * 8 + 2 * (lane & 3);
                const int* a4 = &acc[(t * 2 + u) * 4];
                sep[n * 132 + m]           = a4[0];
                sep[(n + 1) * 132 + m]     = a4[1];
                sep[n * 132 + m + 8]       = a4[2];
                sep[(n + 1) * 132 + m + 8] = a4[3];
            }
        }
    } else {
#pragma unroll
        for (int j = 0; j < 4; j++)
#pragma unroll
            for (int i = 0; i < 8; i++)
                sep[(48 + og * 4 + j) * 132 + pblk * 8 + i] = acc[i * 4 + j];
    }
    __syncthreads();

#pragma unroll 1
    for (int i = 0; i < 8; i++) {
        int ol = wid + i * 8;
        int oc = n0 + ol;
        float sc = d_scale[oc];
        float bv = __ldg(&bias[oc]);
        float* orow = out + ((size_t)(b * OC_ + oc)) * HW_ + q0;
#pragma unroll
        for (int qc = 0; qc < 4; qc++) {
            int m = qc * 32 + lane;
            if (q0 + m < HW_)
                orow[m] = fmaf(sc, (float)sep[ol * 132 + m], bv);
        }
    }
}

// ---------------- launch (conv is the 4th launch for ncu capture) ----------------
extern "C" void kernel_launch(void* const* d_in, const int* in_sizes, int n_in,
                              void* d_out, int out_size) {
    const float* x     = (const float*)d_in[0];
    const float* gamma = (const float*)d_in[1];
    const float* beta  = (const float*)d_in[2];
    const float* a     = (const float*)d_in[3];
    const float* wfp   = (const float*)d_in[4];
    const float* bias  = (const float*)d_in[5];
    float* out = (float*)d_out;
    (void)in_sizes; (void)n_in; (void)out_size;

    tern_kernel<<<OC_, 256>>>(wfp, a);
    gn_stats_kernel<<<B_ * 8, 512>>>(x);
    quant_kernel<<<dim3(110, 8, B_), dim3(32, 8)>>>(x, gamma, beta, a);

    cudaFuncSetAttribute(conv_mma_kernel,
                         cudaFuncAttributeMaxDynamicSharedMemorySize, SMEM_CONV);
    conv_mma_kernel<<<3200, 256, SMEM_CONV>>>(bias, out);
}

// round 15
// speedup vs baseline: 1.1887x; 1.1887x over previous
#include <cuda_runtime.h>
#include <cstdint>
#include <cstddef>

#define B_   32
#define C_   256
#define HW_  3136
#define OC_  256
#define PW   58                            // padded width/height
#define PQ   3492                          // 58*58 + 128 tail pad rows

// ---------------- scratch (device globals) ----------------
__device__ float d_mu[B_ * 8];
__device__ float d_rs[B_ * 8];
__device__ float d_scale[OC_];             // alpha_oc * a_c / 255
__device__ unsigned char d_hq[(size_t)B_ * PQ * 256];   // padded NHWC u8
__device__ signed char  d_ws[9 * 256 * 256];            // [tap][oc][ic] in {-1,0,1}

// ======================= PTX helpers =======================
__device__ __forceinline__ uint32_t smem_u32(const void* p) {
    uint32_t a;
    asm("{ .reg .u64 t; cvta.to.shared.u64 t, %1; cvt.u32.u64 %0, t; }" : "=r"(a) : "l"(p));
    return a;
}
#define CP16(dst, src) \
    asm volatile("cp.async.cg.shared.global [%0], [%1], 16;" :: "r"(dst), "l"(src) : "memory")
#define CP_COMMIT() asm volatile("cp.async.commit_group;" ::: "memory")
#define CP_WAIT3()  asm volatile("cp.async.wait_group 3;" ::: "memory")

__device__ __forceinline__ void ldsm4(uint32_t* r, uint32_t addr) {
    asm volatile("ldmatrix.sync.aligned.m8n8.x4.shared.b16 {%0,%1,%2,%3}, [%4];"
                 : "=r"(r[0]), "=r"(r[1]), "=r"(r[2]), "=r"(r[3]) : "r"(addr));
}
__device__ __forceinline__ void ldsm2(uint32_t* r, uint32_t addr) {
    asm volatile("ldmatrix.sync.aligned.m8n8.x2.shared.b16 {%0,%1}, [%2];"
                 : "=r"(r[0]), "=r"(r[1]) : "r"(addr));
}
__device__ __forceinline__ void mma_u8s8(int* c, const uint32_t* a, const uint32_t* b) {
    asm volatile(
        "mma.sync.aligned.m16n8k32.row.col.s32.u8.s8.s32 "
        "{%0,%1,%2,%3}, {%4,%5,%6,%7}, {%8,%9}, {%0,%1,%2,%3};"
        : "+r"(c[0]), "+r"(c[1]), "+r"(c[2]), "+r"(c[3])
        : "r"(a[0]), "r"(a[1]), "r"(a[2]), "r"(a[3]), "r"(b[0]), "r"(b[1]));
}
__device__ __forceinline__ int dp4a_us(unsigned a, unsigned b, int c) {
    int d;
    asm("dp4a.u32.s32 %0, %1, %2, %3;" : "=r"(d) : "r"(a), "r"(b), "r"(c));
    return d;
}

// ---------------- kernel 1: ternarize weights -> s8 [tap][oc][ic] ----------------
__global__ void tern_kernel(const float* __restrict__ w,
                            const float* __restrict__ a_ptr) {
    int oc = blockIdx.x, tid = threadIdx.x;
    const float* wp = w + (size_t)oc * 2304;
    __shared__ float red[256], red2[256];
    __shared__ float t_sh;

    float s = 0.f;
    for (int i = tid; i < 2304; i += 256) s += fabsf(wp[i]);
    red[tid] = s;
    __syncthreads();
    for (int o = 128; o; o >>= 1) {
        if (tid < o) red[tid] += red[tid + o];
        __syncthreads();
    }
    if (tid == 0) t_sh = 0.05f * red[0] / 2304.0f;
    __syncthreads();
    float t = t_sh;

    float sa = 0.f, sm = 0.f;
    for (int i = tid; i < 2304; i += 256) {
        float aw = fabsf(wp[i]);
        if (aw > t) { sa += aw; sm += 1.f; }
    }
    red[tid] = sa; red2[tid] = sm;
    __syncthreads();
    for (int o = 128; o; o >>= 1) {
        if (tid < o) { red[tid] += red[tid + o]; red2[tid] += red2[tid + o]; }
        __syncthreads();
    }
    if (tid == 0) {
        float alpha = red[0] / (red2[0] + 1e-8f);
        float a_c = fmaxf(a_ptr[0], 0.f) + 1e-8f;
        d_scale[oc] = alpha * a_c / 255.0f;
    }
    for (int i = tid; i < 2304; i += 256) {
        float wv = wp[i];
        signed char q = (fabsf(wv) > t) ? (wv > 0.f ? (signed char)1 : (signed char)-1)
                                        : (signed char)0;
        int ic = i / 9, k = i - ic * 9;    // tap = ky*3+kx
        d_ws[((size_t)k * 256 + oc) * 256 + ic] = q;
    }
}

// ---------------- kernel 2: GroupNorm statistics ----------------
__global__ void gn_stats_kernel(const float* __restrict__ x) {
    int bg = blockIdx.x;
    int b = bg >> 3, g = bg & 7;
    const float4* xp = (const float4*)(x + ((size_t)b * C_ + (size_t)g * 32) * HW_);
    const int N4 = 32 * HW_ / 4;
    int tid = threadIdx.x;
    float s = 0.f, s2 = 0.f;
#pragma unroll 4
    for (int i = tid; i < N4; i += 512) {
        float4 v = xp[i];
        s += v.x + v.y + v.z + v.w;
        s2 += v.x * v.x + v.y * v.y + v.z * v.z + v.w * v.w;
    }
    __shared__ float r1[512], r2[512];
    r1[tid] = s; r2[tid] = s2;
    __syncthreads();
    for (int o = 256; o; o >>= 1) {
        if (tid < o) { r1[tid] += r1[tid + o]; r2[tid] += r2[tid + o]; }
        __syncthreads();
    }
    if (tid == 0) {
        const float N = (float)(32 * HW_);
        float mu = r1[0] / N;
        float var = r2[0] / N - mu * mu;
        d_mu[bg] = mu;
        d_rs[bg] = rsqrtf(var + 1e-5f);
    }
}

// ---------------- kernel 3: GN + ReLU^2 + PACT quant + pad-zero (fused) ----------
// grid (61, 8, 32), block (16,16). x<49: 32ch x 64px tiles, float4 loads,
// uint2 stores; x>=49 (y==0): zero pad rows of d_hq.
__global__ void quant_kernel(const float* __restrict__ x,
                             const float* __restrict__ gamma,
                             const float* __restrict__ beta,
                             const float* __restrict__ a_ptr) {
    int b = blockIdx.z;
    int tx = threadIdx.x, ty = threadIdx.y;   // 16 x 16
    int tid = ty * 16 + tx;

    if (blockIdx.x >= 49) {                // pad-zero blocks
        if (blockIdx.y != 0) return;
        int slot = (blockIdx.x - 49) * 30 + (tid >> 3);
        if (slot >= 356) return;
        int r;
        if (slot < 58)        r = slot;                      // y=0
        else if (slot < 116)  r = 3306 + (slot - 58);        // y=57
        else if (slot < 172)  r = (slot - 115) * PW;         // x=0, y=1..56
        else if (slot < 228)  r = (slot - 171) * PW + 57;    // x=57, y=1..56
        else                  r = 3364 + (slot - 228);       // tail overread rows
        uint4* dst = (uint4*)(d_hq + ((size_t)b * PQ + r) * 256 + (tid & 7) * 32);
        dst[0] = make_uint4(0, 0, 0, 0);
        dst[1] = make_uint4(0, 0, 0, 0);
        return;
    }

    __shared__ unsigned int tile[32][17];  // [channel][px-quad], 4 px bytes per uint
    int c0 = blockIdx.y * 32;
    int p0 = blockIdx.x * 64;

    float a_c = fmaxf(a_ptr[0], 0.f) + 1e-8f;
    float S = 255.f / a_c;
    float mu = d_mu[b * 8 + blockIdx.y];
    float rs = d_rs[b * 8 + blockIdx.y];

#pragma unroll
    for (int ci = 0; ci < 2; ci++) {
        int cl = ci * 16 + ty;
        int c = c0 + cl;
        float ga = gamma[c] * rs, be = beta[c] - mu * gamma[c] * rs;
        float4 v = *(const float4*)(x + ((size_t)b * C_ + c) * HW_ + p0 + tx * 4);
        unsigned int pk = 0;
#pragma unroll
        for (int k = 0; k < 4; k++) {
            float xv = (k == 0) ? v.x : (k == 1) ? v.y : (k == 2) ? v.z : v.w;
            float r = fmaxf(fmaf(xv, ga, be), 0.f);
            float yv = fminf(r * r, a_c);
            pk |= (unsigned int)(int)rintf(yv * S) << (k * 8);
        }
        tile[cl][tx] = pk;
    }
    __syncthreads();

    int px = tid >> 2;                     // 0..63
    int cg = tid & 3;                      // 0..3 (8 channels each)
    int p = p0 + px;
    int y = p / 56, xx = p - y * 56;
    size_t r = (size_t)(y + 1) * PW + xx + 1;
    unsigned int sh = (px & 3) * 8;
    int pq = px >> 2;
    unsigned int u0 = 0, u1 = 0;
#pragma unroll
    for (int k = 0; k < 4; k++) {
        u0 |= ((tile[cg * 8 + k][pq] >> sh) & 255u) << (k * 8);
        u1 |= ((tile[cg * 8 + 4 + k][pq] >> sh) & 255u) << (k * 8);
    }
    *(uint2*)(d_hq + ((size_t)b * PQ + r) * 256 + c0 + cg * 8) = make_uint2(u0, u1);
}

// ---------------- kernel 4: hybrid IMMA + dp4a conv, 128x64 tiles -------------
// 3200 CTAs: b = bid/100, n0 = ((bid%100)/25)*64, q0 = ((bid%100)%25)*128.
// Role: (bid % 3) < 2 -> IMMA. With classic LUT placement, co-resident bids on
// one SM differ by 148/296 -> every SM holds exactly {2 IMMA, 1 dp4a}.
#define NST 5
#define STAGE_B 15360
#define SMEM_CONV (NST * STAGE_B)

__global__ void __launch_bounds__(256, 3)
conv_mma_kernel(const float* __restrict__ bias, float* __restrict__ out) {
    extern __shared__ char smem[];
    uint32_t sbase = smem_u32(smem);
    int tid = threadIdx.x;
    int wid = tid >> 5, lane = tid & 31;
    int bid = blockIdx.x;
    int b = bid / 100;
    int rem = bid - b * 100;
    int n0 = (rem / 25) * 64;
    int q0 = (rem % 25) * 128;
    bool isIMMA = (bid % 3) < 2;

    // loaders: tid<128 -> A row tid; tid in [128,192) -> B row tid-128; else none
    bool isA = tid < 128;
    bool isLd = tid < 192;
    int lrow = isA ? tid : tid - 128;
    int lsw = (lrow >> 3) & 3;
    uint32_t sdst0 = sbase + (isA ? 0u : 10240u) + (uint32_t)lrow * 80u;

    const char* gbase;
    if (isA) {
        int q = q0 + lrow;                 // tail tiles read zeroed pad rows
        int y = q / 56, xx = q - y * 56;
        gbase = (const char*)(d_hq + ((size_t)b * PQ + (size_t)(y * PW + xx)) * 256);
    } else {
        gbase = (const char*)(d_ws + (size_t)(n0 + lrow) * 256);
    }

    auto issue = [&](int s) {
        int st = s % NST;
        if (isLd) {
            int tap = s >> 2, cc = s & 3;
            const char* g;
            if (isA) {
                int ky = tap / 3, kx = tap - ky * 3;
                g = gbase + (size_t)(ky * PW + kx) * 256 + cc * 64;
            } else {
                g = gbase + (size_t)tap * 65536 + cc * 64;
            }
            uint32_t d = sdst0 + (uint32_t)st * STAGE_B;
            CP16(d + ((0 ^ lsw) & 3) * 16, g);
            CP16(d + ((1 ^ lsw) & 3) * 16, g + 16);
            CP16(d + ((2 ^ lsw) & 3) * 16, g + 32);
            CP16(d + ((3 ^ lsw) & 3) * 16, g + 48);
        }
        CP_COMMIT();
    };

    // 32 accumulator regs (disjoint role lifetimes)
    int acc[32];
#pragma unroll
    for (int i = 0; i < 32; i++) acc[i] = 0;

    // ---- IMMA geometry: warp tile 64x16 ----
    int warp_m = wid >> 2, warp_n = wid & 3;
    int grp = lane >> 3, r8 = lane & 7;
    uint32_t a_base[4]; int a_swz[4]; int a_cb = grp >> 1;
#pragma unroll
    for (int t = 0; t < 4; t++) {
        int row = warp_m * 64 + t * 16 + (grp & 1) * 8 + r8;
        a_base[t] = sbase + (uint32_t)row * 80u;
        a_swz[t] = (row >> 3) & 3;
    }
    int bl = lane & 15;
    uint32_t b_base[2]; int b_swz[2]; int b_cb = bl >> 3;
#pragma unroll
    for (int u = 0; u < 2; u++) {
        int row = warp_n * 16 + u * 8 + (bl & 7);
        b_base[u] = sbase + 10240u + (uint32_t)row * 80u;
        b_swz[u] = (row >> 3) & 3;
    }

    // ---- dp4a geometry: 8 pixels x 4 ocs per thread ----
    int tm = tid >> 4, tn = tid & 15;      // pix rows tm*8+i, oc rows tn*4+j
    int tns = tn >> 1;                     // (tn*4+j)>>3 for j<4
    const char* sA = smem;
    const char* sB = smem + 10240;

    issue(0); issue(1); issue(2); issue(3);

#pragma unroll 1
    for (int s = 0; s < 36; s++) {
        int st = s % NST;
        CP_WAIT3();
        __syncthreads();
        if (s + 4 < 36) issue(s + 4);
        else CP_COMMIT();
        uint32_t so = (uint32_t)st * STAGE_B;

        if (isIMMA) {
#pragma unroll
            for (int ks = 0; ks < 2; ks++) {
                uint32_t afr[4][4], bfr[2][2];
#pragma unroll
                for (int t = 0; t < 4; t++) {
                    uint32_t c = (uint32_t)(((ks * 2 + a_cb) ^ a_swz[t]) & 3) * 16u;
                    ldsm4(afr[t], a_base[t] + so + c);
                }
#pragma unroll
                for (int u = 0; u < 2; u++) {
                    uint32_t c = (uint32_t)(((ks * 2 + b_cb) ^ b_swz[u]) & 3) * 16u;
                    ldsm2(bfr[u], b_base[u] + so + c);
                }
#pragma unroll
                for (int t = 0; t < 4; t++)
#pragma unroll
                    for (int u = 0; u < 2; u++)
                        mma_u8s8(&acc[(t * 2 + u) * 4], afr[t], bfr[u]);
            }
        } else {
            const char* pA = sA + so;
            const char* pB = sB + so;
#pragma unroll 1
            for (int kb = 0; kb < 4; kb++) {
                uint32_t ca = (uint32_t)((kb ^ tm) & 3) * 16u;    // av rows>>3 == tm
                uint32_t cb = (uint32_t)((kb ^ tns) & 3) * 16u;   // bv rows>>3 == tn>>1
                uint4 av[8];
#pragma unroll
                for (int i = 0; i < 8; i++)
                    av[i] = *(const uint4*)(pA + (tm * 8 + i) * 80 + ca);
#pragma unroll
                for (int j = 0; j < 4; j++) {
                    uint4 bv = *(const uint4*)(pB + (tn * 4 + j) * 80 + cb);
#pragma unroll
                    for (int i = 0; i < 8; i++) {
                        int v = acc[i * 4 + j];
                        v = dp4a_us(av[i].x, bv.x, v);
                        v = dp4a_us(av[i].y, bv.y, v);
                        v = dp4a_us(av[i].z, bv.z, v);
                        v = dp4a_us(av[i].w, bv.w, v);
                        acc[i * 4 + j] = v;
                    }
                }
            }
        }
    }

    // ---------------- epilogue: stage via smem, coalesced NCHW stores --------
    __syncthreads();
    int* sep = (int*)smem;                // [64 oc][pitch 132]
    if (isIMMA) {
#pragma unroll
        for (int t = 0; t < 4; t++) {
            int m = warp_m * 64 + t * 16 + (lane >> 2);
#pragma unroll
            for (int u = 0; u < 2; u++) {
                int n = warp_n * 16 + u * 8 + 2 * (lane & 3);
                const int* a4 = &acc[(t * 2 + u) * 4];
                sep[n * 132 + m]           = a4[0];
                sep[(n + 1) * 132 + m]     = a4[1];
                sep[n * 132 + m + 8]       = a4[2];
                sep[(n + 1) * 132 + m + 8] = a4[3];
            }
        }
    } else {
#pragma unroll
        for (int j = 0; j < 4; j++)
#pragma unroll
            for (int i = 0; i < 8; i++)
                sep[(tn * 4 + j) * 132 + tm * 8 + i] = acc[i * 4 + j];
    }
    __syncthreads();

#pragma unroll 1
    for (int i = 0; i < 8; i++) {
        int ol = wid + i * 8;
        int oc = n0 + ol;
        float sc = d_scale[oc];
        float bv = __ldg(&bias[oc]);
        float* orow = out + ((size_t)(b * OC_ + oc)) * HW_ + q0;
#pragma unroll
        for (int qc = 0; qc < 4; qc++) {
            int m = qc * 32 + lane;
            if (q0 + m < HW_)
                orow[m] = fmaf(sc, (float)sep[ol * 132 + m], bv);
        }
    }
}

// ---------------- launch (conv is the 4th launch for ncu capture) ----------------
extern "C" void kernel_launch(void* const* d_in, const int* in_sizes, int n_in,
                              void* d_out, int out_size) {
    const float* x     = (const float*)d_in[0];
    const float* gamma = (const float*)d_in[1];
    const float* beta  = (const float*)d_in[2];
    const float* a     = (const float*)d_in[3];
    const float* wfp   = (const float*)d_in[4];
    const float* bias  = (const float*)d_in[5];
    float* out = (float*)d_out;
    (void)in_sizes; (void)n_in; (void)out_size;

    tern_kernel<<<OC_, 256>>>(wfp, a);
    gn_stats_kernel<<<B_ * 8, 512>>>(x);
    quant_kernel<<<dim3(61, 8, B_), dim3(16, 16)>>>(x, gamma, beta, a);

    cudaFuncSetAttribute(conv_mma_kernel,
                         cudaFuncAttributeMaxDynamicSharedMemorySize, SMEM_CONV);
    conv_mma_kernel<<<3200, 256, SMEM_CONV>>>(bias, out);
}

// round 16
// speedup vs baseline: 1.2122x; 1.0197x over previous
#include <cuda_runtime.h>
#include <cstdint>
#include <cstddef>

#define B_   32
#define C_   256
#define HW_  3136
#define OC_  256
#define PW   58                            // padded width/height
#define PQ   3492                          // 58*58 + 128 tail pad rows

// ---------------- scratch (device globals) ----------------
__device__ float d_mu[B_ * 8];
__device__ float d_rs[B_ * 8];
__device__ float d_scale[OC_];             // alpha_oc * a_c / 255
__device__ unsigned char d_hq[(size_t)B_ * PQ * 256];   // padded NHWC u8
__device__ signed char  d_ws[9 * 256 * 256];            // [tap][oc][ic] in {-1,0,1}

// ======================= PTX helpers =======================
__device__ __forceinline__ uint32_t smem_u32(const void* p) {
    uint32_t a;
    asm("{ .reg .u64 t; cvta.to.shared.u64 t, %1; cvt.u32.u64 %0, t; }" : "=r"(a) : "l"(p));
    return a;
}
#define CP16(dst, src) \
    asm volatile("cp.async.cg.shared.global [%0], [%1], 16;" :: "r"(dst), "l"(src) : "memory")
#define CP_COMMIT() asm volatile("cp.async.commit_group;" ::: "memory")
#define CP_WAIT1()  asm volatile("cp.async.wait_group 1;" ::: "memory")

__device__ __forceinline__ void ldsm4(uint32_t* r, uint32_t addr) {
    asm volatile("ldmatrix.sync.aligned.m8n8.x4.shared.b16 {%0,%1,%2,%3}, [%4];"
                 : "=r"(r[0]), "=r"(r[1]), "=r"(r[2]), "=r"(r[3]) : "r"(addr));
}
__device__ __forceinline__ void ldsm2(uint32_t* r, uint32_t addr) {
    asm volatile("ldmatrix.sync.aligned.m8n8.x2.shared.b16 {%0,%1}, [%2];"
                 : "=r"(r[0]), "=r"(r[1]) : "r"(addr));
}
__device__ __forceinline__ void mma_u8s8(int* c, const uint32_t* a, const uint32_t* b) {
    asm volatile(
        "mma.sync.aligned.m16n8k32.row.col.s32.u8.s8.s32 "
        "{%0,%1,%2,%3}, {%4,%5,%6,%7}, {%8,%9}, {%0,%1,%2,%3};"
        : "+r"(c[0]), "+r"(c[1]), "+r"(c[2]), "+r"(c[3])
        : "r"(a[0]), "r"(a[1]), "r"(a[2]), "r"(a[3]), "r"(b[0]), "r"(b[1]));
}
__device__ __forceinline__ int dp4a_us(unsigned a, unsigned b, int c) {
    int d;
    asm("dp4a.u32.s32 %0, %1, %2, %3;" : "=r"(d) : "r"(a), "r"(b), "r"(c));
    return d;
}

// ---------------- kernel 1: ternarize weights -> s8 [tap][oc][ic] ----------------
__global__ void tern_kernel(const float* __restrict__ w,
                            const float* __restrict__ a_ptr) {
    int oc = blockIdx.x, tid = threadIdx.x;
    const float* wp = w + (size_t)oc * 2304;
    __shared__ float red[256], red2[256];
    __shared__ float t_sh;

    float s = 0.f;
    for (int i = tid; i < 2304; i += 256) s += fabsf(wp[i]);
    red[tid] = s;
    __syncthreads();
    for (int o = 128; o; o >>= 1) {
        if (tid < o) red[tid] += red[tid + o];
        __syncthreads();
    }
    if (tid == 0) t_sh = 0.05f * red[0] / 2304.0f;
    __syncthreads();
    float t = t_sh;

    float sa = 0.f, sm = 0.f;
    for (int i = tid; i < 2304; i += 256) {
        float aw = fabsf(wp[i]);
        if (aw > t) { sa += aw; sm += 1.f; }
    }
    red[tid] = sa; red2[tid] = sm;
    __syncthreads();
    for (int o = 128; o; o >>= 1) {
        if (tid < o) { red[tid] += red[tid + o]; red2[tid] += red2[tid + o]; }
        __syncthreads();
    }
    if (tid == 0) {
        float alpha = red[0] / (red2[0] + 1e-8f);
        float a_c = fmaxf(a_ptr[0], 0.f) + 1e-8f;
        d_scale[oc] = alpha * a_c / 255.0f;
    }
    for (int i = tid; i < 2304; i += 256) {
        float wv = wp[i];
        signed char q = (fabsf(wv) > t) ? (wv > 0.f ? (signed char)1 : (signed char)-1)
                                        : (signed char)0;
        int ic = i / 9, k = i - ic * 9;    // tap = ky*3+kx
        d_ws[((size_t)k * 256 + oc) * 256 + ic] = q;
    }
}

// ---------------- kernel 2: GroupNorm statistics ----------------
__global__ void gn_stats_kernel(const float* __restrict__ x) {
    int bg = blockIdx.x;
    int b = bg >> 3, g = bg & 7;
    const float4* xp = (const float4*)(x + ((size_t)b * C_ + (size_t)g * 32) * HW_);
    const int N4 = 32 * HW_ / 4;
    int tid = threadIdx.x;
    float s = 0.f, s2 = 0.f;
#pragma unroll 4
    for (int i = tid; i < N4; i += 512) {
        float4 v = xp[i];
        s += v.x + v.y + v.z + v.w;
        s2 += v.x * v.x + v.y * v.y + v.z * v.z + v.w * v.w;
    }
    __shared__ float r1[512], r2[512];
    r1[tid] = s; r2[tid] = s2;
    __syncthreads();
    for (int o = 256; o; o >>= 1) {
        if (tid < o) { r1[tid] += r1[tid + o]; r2[tid] += r2[tid + o]; }
        __syncthreads();
    }
    if (tid == 0) {
        const float N = (float)(32 * HW_);
        float mu = r1[0] / N;
        float var = r2[0] / N - mu * mu;
        d_mu[bg] = mu;
        d_rs[bg] = rsqrtf(var + 1e-5f);
    }
}

// ---------------- kernel 3: GN + ReLU^2 + PACT quant + pad-zero (fused) ----------
__global__ void quant_kernel(const float* __restrict__ x,
                             const float* __restrict__ gamma,
                             const float* __restrict__ beta,
                             const float* __restrict__ a_ptr) {
    int b = blockIdx.z;
    int tx = threadIdx.x, ty = threadIdx.y;   // 16 x 16
    int tid = ty * 16 + tx;

    if (blockIdx.x >= 49) {                // pad-zero blocks
        if (blockIdx.y != 0) return;
        int slot = (blockIdx.x - 49) * 30 + (tid >> 3);
        if (slot >= 356) return;
        int r;
        if (slot < 58)        r = slot;                      // y=0
        else if (slot < 116)  r = 3306 + (slot - 58);        // y=57
        else if (slot < 172)  r = (slot - 115) * PW;         // x=0, y=1..56
        else if (slot < 228)  r = (slot - 171) * PW + 57;    // x=57, y=1..56
        else                  r = 3364 + (slot - 228);       // tail overread rows
        uint4* dst = (uint4*)(d_hq + ((size_t)b * PQ + r) * 256 + (tid & 7) * 32);
        dst[0] = make_uint4(0, 0, 0, 0);
        dst[1] = make_uint4(0, 0, 0, 0);
        return;
    }

    __shared__ unsigned int tile[32][17];  // [channel][px-quad]
    int c0 = blockIdx.y * 32;
    int p0 = blockIdx.x * 64;

    float a_c = fmaxf(a_ptr[0], 0.f) + 1e-8f;
    float S = 255.f / a_c;
    float mu = d_mu[b * 8 + blockIdx.y];
    float rs = d_rs[b * 8 + blockIdx.y];

#pragma unroll
    for (int ci = 0; ci < 2; ci++) {
        int cl = ci * 16 + ty;
        int c = c0 + cl;
        float ga = gamma[c] * rs, be = beta[c] - mu * gamma[c] * rs;
        float4 v = *(const float4*)(x + ((size_t)b * C_ + c) * HW_ + p0 + tx * 4);
        unsigned int pk = 0;
#pragma unroll
        for (int k = 0; k < 4; k++) {
            float xv = (k == 0) ? v.x : (k == 1) ? v.y : (k == 2) ? v.z : v.w;
            float r = fmaxf(fmaf(xv, ga, be), 0.f);
            float yv = fminf(r * r, a_c);
            pk |= (unsigned int)(int)rintf(yv * S) << (k * 8);
        }
        tile[cl][tx] = pk;
    }
    __syncthreads();

    int px = tid >> 2;
    int cg = tid & 3;
    int p = p0 + px;
    int y = p / 56, xx = p - y * 56;
    size_t r = (size_t)(y + 1) * PW + xx + 1;
    unsigned int sh = (px & 3) * 8;
    int pq = px >> 2;
    unsigned int u0 = 0, u1 = 0;
#pragma unroll
    for (int k = 0; k < 4; k++) {
        u0 |= ((tile[cg * 8 + k][pq] >> sh) & 255u) << (k * 8);
        u1 |= ((tile[cg * 8 + 4 + k][pq] >> sh) & 255u) << (k * 8);
    }
    *(uint2*)(d_hq + ((size_t)b * PQ + r) * 256 + c0 + cg * 8) = make_uint2(u0, u1);
}

// ---------------- kernel 4: hybrid IMMA + dp4a conv, 128x64 tiles -------------
// 3200 CTAs: b = bid/100, n0 = ((bid%100)/25)*64, q0 = ((bid%100)%25)*128.
// Role: (bid % 3) < 2 -> IMMA. NST=3 (46KB/CTA) + forced 64 regs -> 4 CTAs/SM.
// Register diet: IMMA streams afr one ldsm4 at a time; dp4a holds 4 av at once.
#define NST 3
#define STAGE_B 15360
#define SMEM_CONV (NST * STAGE_B)

__global__ void __launch_bounds__(256, 4)
conv_mma_kernel(const float* __restrict__ bias, float* __restrict__ out) {
    extern __shared__ char smem[];
    uint32_t sbase = smem_u32(smem);
    int tid = threadIdx.x;
    int wid = tid >> 5, lane = tid & 31;
    int bid = blockIdx.x;
    int b = bid / 100;
    int rem = bid - b * 100;
    int n0 = (rem / 25) * 64;
    int q0 = (rem % 25) * 128;
    bool isIMMA = (bid % 3) < 2;

    // loaders: tid<128 -> A row tid; tid in [128,192) -> B row tid-128; else none
    bool isA = tid < 128;
    bool isLd = tid < 192;
    int lrow = isA ? tid : tid - 128;
    int lsw = (lrow >> 3) & 3;
    uint32_t sdst0 = sbase + (isA ? 0u : 10240u) + (uint32_t)lrow * 80u;

    const char* gbase;
    if (isA) {
        int q = q0 + lrow;                 // tail tiles read zeroed pad rows
        int y = q / 56, xx = q - y * 56;
        gbase = (const char*)(d_hq + ((size_t)b * PQ + (size_t)(y * PW + xx)) * 256);
    } else {
        gbase = (const char*)(d_ws + (size_t)(n0 + lrow) * 256);
    }

    auto issue = [&](int s) {
        int st = s % NST;
        if (isLd) {
            int tap = s >> 2, cc = s & 3;
            const char* g;
            if (isA) {
                int ky = tap / 3, kx = tap - ky * 3;
                g = gbase + (size_t)(ky * PW + kx) * 256 + cc * 64;
            } else {
                g = gbase + (size_t)tap * 65536 + cc * 64;
            }
            uint32_t d = sdst0 + (uint32_t)st * STAGE_B;
            CP16(d + ((0 ^ lsw) & 3) * 16, g);
            CP16(d + ((1 ^ lsw) & 3) * 16, g + 16);
            CP16(d + ((2 ^ lsw) & 3) * 16, g + 32);
            CP16(d + ((3 ^ lsw) & 3) * 16, g + 48);
        }
        CP_COMMIT();
    };

    // 32 accumulator regs (disjoint role lifetimes)
    int acc[32];
#pragma unroll
    for (int i = 0; i < 32; i++) acc[i] = 0;

    // ---- IMMA geometry: warp tile 64x16 ----
    int warp_m = wid >> 2, warp_n = wid & 3;
    int grp = lane >> 3, r8 = lane & 7;
    uint32_t a_base[4]; int a_swz[4]; int a_cb = grp >> 1;
#pragma unroll
    for (int t = 0; t < 4; t++) {
        int row = warp_m * 64 + t * 16 + (grp & 1) * 8 + r8;
        a_base[t] = sbase + (uint32_t)row * 80u;
        a_swz[t] = (row >> 3) & 3;
    }
    int bl = lane & 15;
    uint32_t b_base[2]; int b_swz[2]; int b_cb = bl >> 3;
#pragma unroll
    for (int u = 0; u < 2; u++) {
        int row = warp_n * 16 + u * 8 + (bl & 7);
        b_base[u] = sbase + 10240u + (uint32_t)row * 80u;
        b_swz[u] = (row >> 3) & 3;
    }

    // ---- dp4a geometry: 8 pixels x 4 ocs per thread ----
    int tm = tid >> 4, tn = tid & 15;      // pix rows tm*8+i, oc rows tn*4+j
    int tns = tn >> 1;                     // (tn*4+j)>>3 for j<4
    const char* sA = smem;
    const char* sB = smem + 10240;

    issue(0); issue(1);

#pragma unroll 1
    for (int s = 0; s < 36; s++) {
        int st = s % NST;
        CP_WAIT1();
        __syncthreads();
        if (s + 2 < 36) issue(s + 2);     // slot (s+2)%3 == (s-1)%3: free
        else CP_COMMIT();
        uint32_t so = (uint32_t)st * STAGE_B;

        if (isIMMA) {
#pragma unroll
            for (int ks = 0; ks < 2; ks++) {
                uint32_t bfr[2][2];
#pragma unroll
                for (int u = 0; u < 2; u++) {
                    uint32_t c = (uint32_t)(((ks * 2 + b_cb) ^ b_swz[u]) & 3) * 16u;
                    ldsm2(bfr[u], b_base[u] + so + c);
                }
#pragma unroll
                for (int t = 0; t < 4; t++) {
                    uint32_t afr[4];
                    uint32_t c = (uint32_t)(((ks * 2 + a_cb) ^ a_swz[t]) & 3) * 16u;
                    ldsm4(afr, a_base[t] + so + c);
                    mma_u8s8(&acc[(t * 2 + 0) * 4], afr, bfr[0]);
                    mma_u8s8(&acc[(t * 2 + 1) * 4], afr, bfr[1]);
                }
            }
        } else {
            const char* pA = sA + so;
            const char* pB = sB + so;
#pragma unroll 1
            for (int kb = 0; kb < 4; kb++) {
                uint32_t ca = (uint32_t)((kb ^ tm) & 3) * 16u;
                uint32_t cb = (uint32_t)((kb ^ tns) & 3) * 16u;
#pragma unroll
                for (int half = 0; half < 2; half++) {
                    uint4 av[4];
#pragma unroll
                    for (int i = 0; i < 4; i++)
                        av[i] = *(const uint4*)(pA + (tm * 8 + half * 4 + i) * 80 + ca);
#pragma unroll
                    for (int j = 0; j < 4; j++) {
                        uint4 bv = *(const uint4*)(pB + (tn * 4 + j) * 80 + cb);
#pragma unroll
                        for (int i = 0; i < 4; i++) {
                            int idx = (half * 4 + i) * 4 + j;
                            int v = acc[idx];
                            v = dp4a_us(av[i].x, bv.x, v);
                            v = dp4a_us(av[i].y, bv.y, v);
                            v = dp4a_us(av[i].z, bv.z, v);
                            v = dp4a_us(av[i].w, bv.w, v);
                            acc[idx] = v;
                        }
                    }
                }
            }
        }
    }

    // ---------------- epilogue: stage via smem, coalesced NCHW stores --------
    __syncthreads();
    int* sep = (int*)smem;                // [64 oc][pitch 132] = 33.8KB <= 46KB
    if (isIMMA) {
#pragma unroll
        for (int t = 0; t < 4; t++) {
            int m = warp_m * 64 + t * 16 + (lane >> 2);
#pragma unroll
            for (int u = 0; u < 2; u++) {
                int n = warp_n * 16 + u * 8 + 2 * (lane & 3);
                const int* a4 = &acc[(t * 2 + u) * 4];
                sep[n * 132 + m]           = a4[0];
                sep[(n + 1) * 132 + m]     = a4[1];
                sep[n * 132 + m + 8]       = a4[2];
                sep[(n + 1) * 132 + m + 8] = a4[3];
            }
        }
    } else {
#pragma unroll
        for (int j = 0; j < 4; j++)
#pragma unroll
            for (int i = 0; i < 8; i++)
                sep[(tn * 4 + j) * 132 + tm * 8 + i] = acc[i * 4 + j];
    }
    __syncthreads();

#pragma unroll 1
    for (int i = 0; i < 8; i++) {
        int ol = wid + i * 8;
        int oc = n0 + ol;
        float sc = d_scale[oc];
        float bv = __ldg(&bias[oc]);
        float* orow = out + ((size_t)(b * OC_ + oc)) * HW_ + q0;
#pragma unroll
        for (int qc = 0; qc < 4; qc++) {
            int m = qc * 32 + lane;
            if (q0 + m < HW_)
                orow[m] = fmaf(sc, (float)sep[ol * 132 + m], bv);
        }
    }
}

// ---------------- launch (conv is the 4th launch for ncu capture) ----------------
extern "C" void kernel_launch(void* const* d_in, const int* in_sizes, int n_in,
                              void* d_out, int out_size) {
    const float* x     = (const float*)d_in[0];
    const float* gamma = (const float*)d_in[1];
    const float* beta  = (const float*)d_in[2];
    const float* a     = (const float*)d_in[3];
    const float* wfp   = (const float*)d_in[4];
    const float* bias  = (const float*)d_in[5];
    float* out = (float*)d_out;
    (void)in_sizes; (void)n_in; (void)out_size;

    tern_kernel<<<OC_, 256>>>(wfp, a);
    gn_stats_kernel<<<B_ * 8, 512>>>(x);
    quant_kernel<<<dim3(61, 8, B_), dim3(16, 16)>>>(x, gamma, beta, a);

    cudaFuncSetAttribute(conv_mma_kernel,
                         cudaFuncAttributeMaxDynamicSharedMemorySize, SMEM_CONV);
    conv_mma_kernel<<<3200, 256, SMEM_CONV>>>(bias, out);
}

// round 17
// speedup vs baseline: 1.2433x; 1.0257x over previous
#include <cuda_runtime.h>
#include <cstdint>
#include <cstddef>

#define B_   32
#define C_   256
#define HW_  3136
#define OC_  256
#define PW   58                            // padded width/height
#define PQ   3492                          // 58*58 + 128 tail pad rows

// ---------------- scratch (device globals) ----------------
__device__ float d_mu[B_ * 8];
__device__ float d_rs[B_ * 8];
__device__ float d_scale[OC_];             // alpha_oc * a_c / 255
__device__ unsigned char d_hq[(size_t)B_ * PQ * 256];   // padded NHWC u8
__device__ signed char  d_ws[9 * 256 * 256];            // [tap][oc][ic] in {-1,0,1}

// ======================= PTX helpers =======================
__device__ __forceinline__ uint32_t smem_u32(const void* p) {
    uint32_t a;
    asm("{ .reg .u64 t; cvta.to.shared.u64 t, %1; cvt.u32.u64 %0, t; }" : "=r"(a) : "l"(p));
    return a;
}
#define CP16(dst, src) \
    asm volatile("cp.async.cg.shared.global [%0], [%1], 16;" :: "r"(dst), "l"(src) : "memory")
#define CP_COMMIT() asm volatile("cp.async.commit_group;" ::: "memory")
#define CP_WAIT1()  asm volatile("cp.async.wait_group 1;" ::: "memory")

__device__ __forceinline__ void ldsm4(uint32_t* r, uint32_t addr) {
    asm volatile("ldmatrix.sync.aligned.m8n8.x4.shared.b16 {%0,%1,%2,%3}, [%4];"
                 : "=r"(r[0]), "=r"(r[1]), "=r"(r[2]), "=r"(r[3]) : "r"(addr));
}
__device__ __forceinline__ void ldsm2(uint32_t* r, uint32_t addr) {
    asm volatile("ldmatrix.sync.aligned.m8n8.x2.shared.b16 {%0,%1}, [%2];"
                 : "=r"(r[0]), "=r"(r[1]) : "r"(addr));
}
__device__ __forceinline__ void mma_u8s8(int* c, const uint32_t* a, const uint32_t* b) {
    asm volatile(
        "mma.sync.aligned.m16n8k32.row.col.s32.u8.s8.s32 "
        "{%0,%1,%2,%3}, {%4,%5,%6,%7}, {%8,%9}, {%0,%1,%2,%3};"
        : "+r"(c[0]), "+r"(c[1]), "+r"(c[2]), "+r"(c[3])
        : "r"(a[0]), "r"(a[1]), "r"(a[2]), "r"(a[3]), "r"(b[0]), "r"(b[1]));
}
__device__ __forceinline__ int dp4a_us(unsigned a, unsigned b, int c) {
    int d;
    asm("dp4a.u32.s32 %0, %1, %2, %3;" : "=r"(d) : "r"(a), "r"(b), "r"(c));
    return d;
}

// ---------------- kernel 1: ternarize weights -> s8 [tap][oc][ic] ----------------
__global__ void tern_kernel(const float* __restrict__ w,
                            const float* __restrict__ a_ptr) {
    int oc = blockIdx.x, tid = threadIdx.x;
    const float* wp = w + (size_t)oc * 2304;
    __shared__ float red[256], red2[256];
    __shared__ float t_sh;

    float s = 0.f;
    for (int i = tid; i < 2304; i += 256) s += fabsf(wp[i]);
    red[tid] = s;
    __syncthreads();
    for (int o = 128; o; o >>= 1) {
        if (tid < o) red[tid] += red[tid + o];
        __syncthreads();
    }
    if (tid == 0) t_sh = 0.05f * red[0] / 2304.0f;
    __syncthreads();
    float t = t_sh;

    float sa = 0.f, sm = 0.f;
    for (int i = tid; i < 2304; i += 256) {
        float aw = fabsf(wp[i]);
        if (aw > t) { sa += aw; sm += 1.f; }
    }
    red[tid] = sa; red2[tid] = sm;
    __syncthreads();
    for (int o = 128; o; o >>= 1) {
        if (tid < o) { red[tid] += red[tid + o]; red2[tid] += red2[tid + o]; }
        __syncthreads();
    }
    if (tid == 0) {
        float alpha = red[0] / (red2[0] + 1e-8f);
        float a_c = fmaxf(a_ptr[0], 0.f) + 1e-8f;
        d_scale[oc] = alpha * a_c / 255.0f;
    }
    for (int i = tid; i < 2304; i += 256) {
        float wv = wp[i];
        signed char q = (fabsf(wv) > t) ? (wv > 0.f ? (signed char)1 : (signed char)-1)
                                        : (signed char)0;
        int ic = i / 9, k = i - ic * 9;    // tap = ky*3+kx
        d_ws[((size_t)k * 256 + oc) * 256 + ic] = q;
    }
}

// ---------------- kernel 2: GroupNorm statistics ----------------
__global__ void gn_stats_kernel(const float* __restrict__ x) {
    int bg = blockIdx.x;
    int b = bg >> 3, g = bg & 7;
    const float4* xp = (const float4*)(x + ((size_t)b * C_ + (size_t)g * 32) * HW_);
    const int N4 = 32 * HW_ / 4;
    int tid = threadIdx.x;
    float s = 0.f, s2 = 0.f;
#pragma unroll 4
    for (int i = tid; i < N4; i += 512) {
        float4 v = xp[i];
        s += v.x + v.y + v.z + v.w;
        s2 += v.x * v.x + v.y * v.y + v.z * v.z + v.w * v.w;
    }
    __shared__ float r1[512], r2[512];
    r1[tid] = s; r2[tid] = s2;
    __syncthreads();
    for (int o = 256; o; o >>= 1) {
        if (tid < o) { r1[tid] += r1[tid + o]; r2[tid] += r2[tid + o]; }
        __syncthreads();
    }
    if (tid == 0) {
        const float N = (float)(32 * HW_);
        float mu = r1[0] / N;
        float var = r2[0] / N - mu * mu;
        d_mu[bg] = mu;
        d_rs[bg] = rsqrtf(var + 1e-5f);
    }
}

// ---------------- kernel 3: GN + ReLU^2 + PACT quant + pad-zero (fused) ----------
__global__ void quant_kernel(const float* __restrict__ x,
                             const float* __restrict__ gamma,
                             const float* __restrict__ beta,
                             const float* __restrict__ a_ptr) {
    int b = blockIdx.z;
    int tx = threadIdx.x, ty = threadIdx.y;   // 16 x 16
    int tid = ty * 16 + tx;

    if (blockIdx.x >= 49) {                // pad-zero blocks
        if (blockIdx.y != 0) return;
        int slot = (blockIdx.x - 49) * 30 + (tid >> 3);
        if (slot >= 356) return;
        int r;
        if (slot < 58)        r = slot;                      // y=0
        else if (slot < 116)  r = 3306 + (slot - 58);        // y=57
        else if (slot < 172)  r = (slot - 115) * PW;         // x=0, y=1..56
        else if (slot < 228)  r = (slot - 171) * PW + 57;    // x=57, y=1..56
        else                  r = 3364 + (slot - 228);       // tail overread rows
        uint4* dst = (uint4*)(d_hq + ((size_t)b * PQ + r) * 256 + (tid & 7) * 32);
        dst[0] = make_uint4(0, 0, 0, 0);
        dst[1] = make_uint4(0, 0, 0, 0);
        return;
    }

    __shared__ unsigned int tile[32][17];  // [channel][px-quad]
    int c0 = blockIdx.y * 32;
    int p0 = blockIdx.x * 64;

    float a_c = fmaxf(a_ptr[0], 0.f) + 1e-8f;
    float S = 255.f / a_c;
    float mu = d_mu[b * 8 + blockIdx.y];
    float rs = d_rs[b * 8 + blockIdx.y];

#pragma unroll
    for (int ci = 0; ci < 2; ci++) {
        int cl = ci * 16 + ty;
        int c = c0 + cl;
        float ga = gamma[c] * rs, be = beta[c] - mu * gamma[c] * rs;
        float4 v = *(const float4*)(x + ((size_t)b * C_ + c) * HW_ + p0 + tx * 4);
        unsigned int pk = 0;
#pragma unroll
        for (int k = 0; k < 4; k++) {
            float xv = (k == 0) ? v.x : (k == 1) ? v.y : (k == 2) ? v.z : v.w;
            float r = fmaxf(fmaf(xv, ga, be), 0.f);
            float yv = fminf(r * r, a_c);
            pk |= (unsigned int)(int)rintf(yv * S) << (k * 8);
        }
        tile[cl][tx] = pk;
    }
    __syncthreads();

    int px = tid >> 2;
    int cg = tid & 3;
    int p = p0 + px;
    int y = p / 56, xx = p - y * 56;
    size_t r = (size_t)(y + 1) * PW + xx + 1;
    unsigned int sh = (px & 3) * 8;
    int pq = px >> 2;
    unsigned int u0 = 0, u1 = 0;
#pragma unroll
    for (int k = 0; k < 4; k++) {
        u0 |= ((tile[cg * 8 + k][pq] >> sh) & 255u) << (k * 8);
        u1 |= ((tile[cg * 8 + 4 + k][pq] >> sh) & 255u) << (k * 8);
    }
    *(uint2*)(d_hq + ((size_t)b * PQ + r) * 256 + c0 + cg * 8) = make_uint2(u0, u1);
}

// ---------------- kernel 4: hybrid IMMA + dp4a conv, 128x64 tiles -------------
// 3200 CTAs: b = bid/100, n0 = ((bid%100)/25)*64, q0 = ((bid%100)%25)*128.
// Role: wave parity (bid/152)&1 -> alternating waves of IMMA / dp4a, so the
// 4 co-resident CTAs per SM (consecutive waves) are exactly {2 IMMA, 2 dp4a}
// and the global split is ~50:50 (shifts ~500 tiles off the saturated tensor
// pipe onto the slack fma pipe). NST=3, 4 CTAs/SM, 64 regs.
#define NST 3
#define STAGE_B 15360
#define SMEM_CONV (NST * STAGE_B)

__global__ void __launch_bounds__(256, 4)
conv_mma_kernel(const float* __restrict__ bias, float* __restrict__ out) {
    extern __shared__ char smem[];
    uint32_t sbase = smem_u32(smem);
    int tid = threadIdx.x;
    int wid = tid >> 5, lane = tid & 31;
    int bid = blockIdx.x;
    int b = bid / 100;
    int rem = bid - b * 100;
    int n0 = (rem / 25) * 64;
    int q0 = (rem % 25) * 128;
    bool isIMMA = ((bid / 152) & 1) == 0;

    // loaders: tid<128 -> A row tid; tid in [128,192) -> B row tid-128; else none
    bool isA = tid < 128;
    bool isLd = tid < 192;
    int lrow = isA ? tid : tid - 128;
    int lsw = (lrow >> 3) & 3;
    uint32_t sdst0 = sbase + (isA ? 0u : 10240u) + (uint32_t)lrow * 80u;

    const char* gbase;
    if (isA) {
        int q = q0 + lrow;                 // tail tiles read zeroed pad rows
        int y = q / 56, xx = q - y * 56;
        gbase = (const char*)(d_hq + ((size_t)b * PQ + (size_t)(y * PW + xx)) * 256);
    } else {
        gbase = (const char*)(d_ws + (size_t)(n0 + lrow) * 256);
    }

    auto issue = [&](int s) {
        int st = s % NST;
        if (isLd) {
            int tap = s >> 2, cc = s & 3;
            const char* g;
            if (isA) {
                int ky = tap / 3, kx = tap - ky * 3;
                g = gbase + (size_t)(ky * PW + kx) * 256 + cc * 64;
            } else {
                g = gbase + (size_t)tap * 65536 + cc * 64;
            }
            uint32_t d = sdst0 + (uint32_t)st * STAGE_B;
            CP16(d + ((0 ^ lsw) & 3) * 16, g);
            CP16(d + ((1 ^ lsw) & 3) * 16, g + 16);
            CP16(d + ((2 ^ lsw) & 3) * 16, g + 32);
            CP16(d + ((3 ^ lsw) & 3) * 16, g + 48);
        }
        CP_COMMIT();
    };

    // 32 accumulator regs (disjoint role lifetimes)
    int acc[32];
#pragma unroll
    for (int i = 0; i < 32; i++) acc[i] = 0;

    // ---- IMMA geometry: warp tile 64x16 ----
    int warp_m = wid >> 2, warp_n = wid & 3;
    int grp = lane >> 3, r8 = lane & 7;
    uint32_t a_base[4]; int a_swz[4]; int a_cb = grp >> 1;
#pragma unroll
    for (int t = 0; t < 4; t++) {
        int row = warp_m * 64 + t * 16 + (grp & 1) * 8 + r8;
        a_base[t] = sbase + (uint32_t)row * 80u;
        a_swz[t] = (row >> 3) & 3;
    }
    int bl = lane & 15;
    uint32_t b_base[2]; int b_swz[2]; int b_cb = bl >> 3;
#pragma unroll
    for (int u = 0; u < 2; u++) {
        int row = warp_n * 16 + u * 8 + (bl & 7);
        b_base[u] = sbase + 10240u + (uint32_t)row * 80u;
        b_swz[u] = (row >> 3) & 3;
    }

    // ---- dp4a geometry: 8 pixels x 4 ocs per thread ----
    int tm = tid >> 4, tn = tid & 15;      // pix rows tm*8+i, oc rows tn*4+j
    int tns = tn >> 1;                     // (tn*4+j)>>3 for j<4
    const char* sA = smem;
    const char* sB = smem + 10240;

    issue(0); issue(1);

#pragma unroll 1
    for (int s = 0; s < 36; s++) {
        int st = s % NST;
        CP_WAIT1();
        __syncthreads();
        if (s + 2 < 36) issue(s + 2);     // slot (s+2)%3 == (s-1)%3: free
        else CP_COMMIT();
        uint32_t so = (uint32_t)st * STAGE_B;

        if (isIMMA) {
#pragma unroll
            for (int ks = 0; ks < 2; ks++) {
                uint32_t bfr[2][2];
#pragma unroll
                for (int u = 0; u < 2; u++) {
                    uint32_t c = (uint32_t)(((ks * 2 + b_cb) ^ b_swz[u]) & 3) * 16u;
                    ldsm2(bfr[u], b_base[u] + so + c);
                }
#pragma unroll
                for (int t = 0; t < 4; t++) {
                    uint32_t afr[4];
                    uint32_t c = (uint32_t)(((ks * 2 + a_cb) ^ a_swz[t]) & 3) * 16u;
                    ldsm4(afr, a_base[t] + so + c);
                    mma_u8s8(&acc[(t * 2 + 0) * 4], afr, bfr[0]);
                    mma_u8s8(&acc[(t * 2 + 1) * 4], afr, bfr[1]);
                }
            }
        } else {
            const char* pA = sA + so;
            const char* pB = sB + so;
#pragma unroll 1
            for (int kb = 0; kb < 4; kb++) {
                uint32_t ca = (uint32_t)((kb ^ tm) & 3) * 16u;
                uint32_t cb = (uint32_t)((kb ^ tns) & 3) * 16u;
#pragma unroll
                for (int half = 0; half < 2; half++) {
                    uint4 av[4];
#pragma unroll
                    for (int i = 0; i < 4; i++)
                        av[i] = *(const uint4*)(pA + (tm * 8 + half * 4 + i) * 80 + ca);
#pragma unroll
                    for (int j = 0; j < 4; j++) {
                        uint4 bv = *(const uint4*)(pB + (tn * 4 + j) * 80 + cb);
#pragma unroll
                        for (int i = 0; i < 4; i++) {
                            int idx = (half * 4 + i) * 4 + j;
                            int v = acc[idx];
                            v = dp4a_us(av[i].x, bv.x, v);
                            v = dp4a_us(av[i].y, bv.y, v);
                            v = dp4a_us(av[i].z, bv.z, v);
                            v = dp4a_us(av[i].w, bv.w, v);
                            acc[idx] = v;
                        }
                    }
                }
            }
        }
    }

    // ---------------- epilogue: stage via smem, coalesced NCHW stores --------
    __syncthreads();
    int* sep = (int*)smem;                // [64 oc][pitch 132] = 33.8KB <= 46KB
    if (isIMMA) {
#pragma unroll
        for (int t = 0; t < 4; t++) {
            int m = warp_m * 64 + t * 16 + (lane >> 2);
#pragma unroll
            for (int u = 0; u < 2; u++) {
                int n = warp_n * 16 + u * 8 + 2 * (lane & 3);
                const int* a4 = &acc[(t * 2 + u) * 4];
                sep[n * 132 + m]           = a4[0];
                sep[(n + 1) * 132 + m]     = a4[1];
                sep[n * 132 + m + 8]       = a4[2];
                sep[(n + 1) * 132 + m + 8] = a4[3];
            }
        }
    } else {
#pragma unroll
        for (int j = 0; j < 4; j++)
#pragma unroll
            for (int i = 0; i < 8; i++)
                sep[(tn * 4 + j) * 132 + tm * 8 + i] = acc[i * 4 + j];
    }
    __syncthreads();

#pragma unroll 1
    for (int i = 0; i < 8; i++) {
        int ol = wid + i * 8;
        int oc = n0 + ol;
        float sc = d_scale[oc];
        float bv = __ldg(&bias[oc]);
        float* orow = out + ((size_t)(b * OC_ + oc)) * HW_ + q0;
#pragma unroll
        for (int qc = 0; qc < 4; qc++) {
            int m = qc * 32 + lane;
            if (q0 + m < HW_)
                orow[m] = fmaf(sc, (float)sep[ol * 132 + m], bv);
        }
    }
}

// ---------------- launch (conv is the 4th launch for ncu capture) ----------------
extern "C" void kernel_launch(void* const* d_in, const int* in_sizes, int n_in,
                              void* d_out, int out_size) {
    const float* x     = (const float*)d_in[0];
    const float* gamma = (const float*)d_in[1];
    const float* beta  = (const float*)d_in[2];
    const float* a     = (const float*)d_in[3];
    const float* wfp   = (const float*)d_in[4];
    const float* bias  = (const float*)d_in[5];
    float* out = (float*)d_out;
    (void)in_sizes; (void)n_in; (void)out_size;

    tern_kernel<<<OC_, 256>>>(wfp, a);
    gn_stats_kernel<<<B_ * 8, 512>>>(x);
    quant_kernel<<<dim3(61, 8, B_), dim3(16, 16)>>>(x, gamma, beta, a);

    cudaFuncSetAttribute(conv_mma_kernel,
                         cudaFuncAttributeMaxDynamicSharedMemorySize, SMEM_CONV);
    conv_mma_kernel<<<3200, 256, SMEM_CONV>>>(bias, out);
}